// round 2
// baseline (speedup 1.0000x reference)
#include <cuda_runtime.h>
#include <cuda_bf16.h>

// Problem constants
#define BB 2
#define TT 4096
#define EE 768
#define HH 12
#define SS 64
#define WW 256
#define CC 16          // TT / WW
#define NN (BB * TT)   // 8192

// Scratch (device globals: allocation-free). 25.2 MB each, 75 MB total.
__device__ float g_q[(size_t)BB * HH * TT * SS];   // [b][h][t][d]
__device__ float g_k[(size_t)BB * HH * TT * SS];
__device__ float g_v[(size_t)BB * HH * TT * SS];

// ---------------------------------------------------------------------------
// Pass 1: Q/K/V = x @ W^T  (z selects which), output layout [b][h][t][d]
// 128x128 tile, BK=8, 256 threads, 8x8 per thread
// ---------------------------------------------------------------------------
__global__ __launch_bounds__(256) void qkv_kernel(
    const float* __restrict__ x,
    const float* __restrict__ wq,
    const float* __restrict__ wk,
    const float* __restrict__ wv)
{
    __shared__ float As[8][132];
    __shared__ float Bs[8][132];

    const int which = blockIdx.z;
    const float* Wm = (which == 0) ? wq : (which == 1) ? wk : wv;
    float* dst = (which == 0) ? g_q : (which == 1) ? g_k : g_v;
    const float scale = (which == 0) ? 0.125f : 1.0f;  // 1/sqrt(64)

    const int rowBase = blockIdx.x * 128;
    const int colBase = blockIdx.y * 128;
    const int t  = threadIdx.x;
    const int tx = t & 15;
    const int ty = t >> 4;
    const int lr  = t >> 1;
    const int lk4 = (t & 1) * 4;

    float acc[8][8];
    #pragma unroll
    for (int i = 0; i < 8; i++)
        #pragma unroll
        for (int j = 0; j < 8; j++) acc[i][j] = 0.0f;

    for (int k0 = 0; k0 < EE; k0 += 8) {
        float4 av = *(const float4*)&x [(rowBase + lr) * EE + k0 + lk4];
        float4 bv = *(const float4*)&Wm[(colBase + lr) * EE + k0 + lk4];
        __syncthreads();
        As[lk4 + 0][lr] = av.x; As[lk4 + 1][lr] = av.y;
        As[lk4 + 2][lr] = av.z; As[lk4 + 3][lr] = av.w;
        Bs[lk4 + 0][lr] = bv.x; Bs[lk4 + 1][lr] = bv.y;
        Bs[lk4 + 2][lr] = bv.z; Bs[lk4 + 3][lr] = bv.w;
        __syncthreads();
        #pragma unroll
        for (int kk = 0; kk < 8; kk++) {
            float a[8], b[8];
            #pragma unroll
            for (int i = 0; i < 8; i++) a[i] = As[kk][ty * 8 + i];
            #pragma unroll
            for (int j = 0; j < 8; j++) b[j] = Bs[kk][tx * 8 + j];
            #pragma unroll
            for (int i = 0; i < 8; i++)
                #pragma unroll
                for (int j = 0; j < 8; j++) acc[i][j] += a[i] * b[j];
        }
    }

    #pragma unroll
    for (int i = 0; i < 8; i++) {
        const int n  = rowBase + ty * 8 + i;
        const int bb = n >> 12;         // n / TT
        const int tt = n & (TT - 1);
        #pragma unroll
        for (int j = 0; j < 8; j++) {
            const int jc = colBase + tx * 8 + j;
            const int h  = jc >> 6;
            const int d  = jc & 63;
            dst[(((size_t)(bb * HH + h) * TT) + tt) * SS + d] = acc[i][j] * scale;
        }
    }
}

// ---------------------------------------------------------------------------
// Pass 2: fused flash-style attention.
// Block = 128 queries (half a chunk) x one (b,h). Online softmax over 6 key
// tiles of 128 (prev/cur/next chunk). Zero-padded chunks contribute score 0
// (except triangular boundary mask = -1e30) to the softmax denominator, with
// V = 0, matching the reference exactly.
// ---------------------------------------------------------------------------
#define QK_STRIDE 132
#define V_STRIDE  68
#define P_STRIDE  132
#define SM_K  (64 * QK_STRIDE)
#define SM_V  (SM_K + 64 * QK_STRIDE)
#define SM_P  (SM_V + 128 * V_STRIDE)
#define SMEM_FLOATS (SM_P + 128 * P_STRIDE)
#define SMEM_BYTES  (SMEM_FLOATS * 4)

__global__ __launch_bounds__(256) void attn_kernel(float* __restrict__ out)
{
    extern __shared__ float sm[];
    float* Qs = sm;           // [64][QK_STRIDE]  Q transposed: Qs[d][row]
    float* Ks = sm + SM_K;    // [64][QK_STRIDE]  K transposed: Ks[d][col]
    float* Vs = sm + SM_V;    // [128][V_STRIDE]  V straight:  Vs[key][d]
    float* Ps = sm + SM_P;    // [128][P_STRIDE]  P:           Ps[row][key]

    const int c    = blockIdx.x >> 1;
    const int half = blockIdx.x & 1;
    const int bh   = blockIdx.y;
    const int b = bh / HH;
    const int h = bh % HH;

    const int t  = threadIdx.x;
    const int tx = t & 15;
    const int ty = t >> 4;

    const float* qptr = g_q + ((size_t)bh * TT + c * WW + half * 128) * SS;

    // Load Q tile transposed into SMEM (128 rows x 64 d)
    #pragma unroll
    for (int i = 0; i < 8; i++) {
        const int q  = t + i * 256;       // 0..2047
        const int r  = q >> 4;
        const int d4 = (q & 15) * 4;
        float4 v = *(const float4*)&qptr[r * SS + d4];
        Qs[(d4 + 0) * QK_STRIDE + r] = v.x;
        Qs[(d4 + 1) * QK_STRIDE + r] = v.y;
        Qs[(d4 + 2) * QK_STRIDE + r] = v.z;
        Qs[(d4 + 3) * QK_STRIDE + r] = v.w;
    }

    float m[8], l[8], o[8][4];
    #pragma unroll
    for (int i = 0; i < 8; i++) {
        m[i] = -1e30f; l[i] = 0.0f;
        #pragma unroll
        for (int j = 0; j < 4; j++) o[i][j] = 0.0f;
    }

    const int x0 = half * 128 + ty * 8;   // query index within chunk, base

    for (int nt = 0; nt < 6; nt++) {
        const int kc = c - 1 + (nt >> 1);
        const bool valid = (kc >= 0) && (kc < CC);
        const int y0 = (nt & 1) * 128;

        float s[8][8];

        if (valid) {
            const float* kptr = g_k + ((size_t)bh * TT + kc * WW + y0) * SS;
            const float* vptr = g_v + ((size_t)bh * TT + kc * WW + y0) * SS;
            __syncthreads();   // previous tile's PV reads done
            #pragma unroll
            for (int i = 0; i < 8; i++) {
                const int q  = t + i * 256;
                const int r  = q >> 4;
                const int d4 = (q & 15) * 4;
                float4 kv = *(const float4*)&kptr[r * SS + d4];
                Ks[(d4 + 0) * QK_STRIDE + r] = kv.x;
                Ks[(d4 + 1) * QK_STRIDE + r] = kv.y;
                Ks[(d4 + 2) * QK_STRIDE + r] = kv.z;
                Ks[(d4 + 3) * QK_STRIDE + r] = kv.w;
                *(float4*)&Vs[r * V_STRIDE + d4] = *(const float4*)&vptr[r * SS + d4];
            }
            __syncthreads();

            #pragma unroll
            for (int i = 0; i < 8; i++)
                #pragma unroll
                for (int j = 0; j < 8; j++) s[i][j] = 0.0f;

            #pragma unroll 4
            for (int kk = 0; kk < 64; kk++) {
                float4 a0 = *(const float4*)&Qs[kk * QK_STRIDE + ty * 8];
                float4 a1 = *(const float4*)&Qs[kk * QK_STRIDE + ty * 8 + 4];
                float4 b0 = *(const float4*)&Ks[kk * QK_STRIDE + tx * 8];
                float4 b1 = *(const float4*)&Ks[kk * QK_STRIDE + tx * 8 + 4];
                const float a[8] = {a0.x, a0.y, a0.z, a0.w, a1.x, a1.y, a1.z, a1.w};
                const float bb[8] = {b0.x, b0.y, b0.z, b0.w, b1.x, b1.y, b1.z, b1.w};
                #pragma unroll
                for (int i = 0; i < 8; i++)
                    #pragma unroll
                    for (int j = 0; j < 8; j++) s[i][j] += a[i] * bb[j];
            }
        } else {
            // Zero-padded neighbor chunk: score 0 except boundary mask.
            // Only happens for c==0 (nt 0,1) or c==CC-1 (nt 4,5).
            #pragma unroll
            for (int i = 0; i < 8; i++) {
                const int xq = x0 + i;
                #pragma unroll
                for (int j = 0; j < 8; j++) {
                    const int jg = nt * 128 + tx * 8 + j;
                    const bool msk = (c == 0) ? (jg < WW - xq)
                                              : (jg >= 3 * WW - 1 - xq);
                    s[i][j] = msk ? -1e30f : 0.0f;
                }
            }
        }

        // Online softmax update (row groups of 16 threads share ty; lane-xor
        // masks 1,2,4,8 stay inside the 16-thread group)
        #pragma unroll
        for (int i = 0; i < 8; i++) {
            float rm = s[i][0];
            #pragma unroll
            for (int j = 1; j < 8; j++) rm = fmaxf(rm, s[i][j]);
            #pragma unroll
            for (int off = 8; off > 0; off >>= 1)
                rm = fmaxf(rm, __shfl_xor_sync(0xFFFFFFFFu, rm, off));
            const float mn    = fmaxf(m[i], rm);
            const float alpha = __expf(m[i] - mn);
            float rs = 0.0f;
            #pragma unroll
            for (int j = 0; j < 8; j++) {
                s[i][j] = __expf(s[i][j] - mn);
                rs += s[i][j];
            }
            #pragma unroll
            for (int off = 8; off > 0; off >>= 1)
                rs += __shfl_xor_sync(0xFFFFFFFFu, rs, off);
            l[i] = l[i] * alpha + rs;
            m[i] = mn;
            #pragma unroll
            for (int j = 0; j < 4; j++) o[i][j] *= alpha;
        }

        if (valid) {
            // Write P to SMEM, then accumulate O += P @ V
            #pragma unroll
            for (int i = 0; i < 8; i++) {
                *(float4*)&Ps[(ty * 8 + i) * P_STRIDE + tx * 8] =
                    make_float4(s[i][0], s[i][1], s[i][2], s[i][3]);
                *(float4*)&Ps[(ty * 8 + i) * P_STRIDE + tx * 8 + 4] =
                    make_float4(s[i][4], s[i][5], s[i][6], s[i][7]);
            }
            __syncthreads();

            #pragma unroll 2
            for (int kk = 0; kk < 128; kk += 4) {
                float bv[4][4];
                #pragma unroll
                for (int u = 0; u < 4; u++) {
                    float4 vv = *(const float4*)&Vs[(kk + u) * V_STRIDE + tx * 4];
                    bv[u][0] = vv.x; bv[u][1] = vv.y; bv[u][2] = vv.z; bv[u][3] = vv.w;
                }
                #pragma unroll
                for (int i = 0; i < 8; i++) {
                    float4 a4 = *(const float4*)&Ps[(ty * 8 + i) * P_STRIDE + kk];
                    #pragma unroll
                    for (int j = 0; j < 4; j++) {
                        o[i][j] += a4.x * bv[0][j];
                        o[i][j] += a4.y * bv[1][j];
                        o[i][j] += a4.z * bv[2][j];
                        o[i][j] += a4.w * bv[3][j];
                    }
                }
            }
        }
    }

    // Final normalize + write: out[b][t][h*64 + d]
    #pragma unroll
    for (int i = 0; i < 8; i++) {
        const float inv = 1.0f / l[i];
        const int trow = c * WW + half * 128 + ty * 8 + i;
        *(float4*)&out[((size_t)b * TT + trow) * EE + h * SS + tx * 4] =
            make_float4(o[i][0] * inv, o[i][1] * inv, o[i][2] * inv, o[i][3] * inv);
    }
}

// ---------------------------------------------------------------------------
extern "C" void kernel_launch(void* const* d_in, const int* in_sizes, int n_in,
                              void* d_out, int out_size)
{
    const float* x  = (const float*)d_in[0];
    const float* wq = (const float*)d_in[1];
    const float* wk = (const float*)d_in[2];
    const float* wv = (const float*)d_in[3];
    float* out = (float*)d_out;

    cudaFuncSetAttribute(attn_kernel,
                         cudaFuncAttributeMaxDynamicSharedMemorySize, SMEM_BYTES);

    qkv_kernel<<<dim3(NN / 128, EE / 128, 3), 256>>>(x, wq, wk, wv);
    attn_kernel<<<dim3(2 * CC, BB * HH), 256, SMEM_BYTES>>>(out);
}

// round 3
// speedup vs baseline: 1.0016x; 1.0016x over previous
#include <cuda_runtime.h>
#include <cuda_bf16.h>

// Problem constants
#define BB 2
#define TT 4096
#define EE 768
#define HH 12
#define SS 64
#define WW 256
#define CC 16          // TT / WW
#define NN (BB * TT)   // 8192

// ---------------------------------------------------------------------------
// Packed fp32x2 helpers (Blackwell FFMA2 path; IEEE-identical to scalar FFMA)
// ---------------------------------------------------------------------------
typedef unsigned long long f32x2_t;

__device__ __forceinline__ f32x2_t pk2(float lo, float hi) {
    f32x2_t r;
    asm("mov.b64 %0, {%1, %2};" : "=l"(r) : "f"(lo), "f"(hi));
    return r;
}
__device__ __forceinline__ f32x2_t dup2(float v) { return pk2(v, v); }
__device__ __forceinline__ void upk2(f32x2_t v, float& lo, float& hi) {
    asm("mov.b64 {%0, %1}, %2;" : "=f"(lo), "=f"(hi) : "l"(v));
}
__device__ __forceinline__ void fma2(f32x2_t& d, f32x2_t a, f32x2_t b) {
    asm("fma.rn.f32x2 %0, %1, %2, %0;" : "+l"(d) : "l"(a), "l"(b));
}
__device__ __forceinline__ void mul2(f32x2_t& d, f32x2_t a) {
    asm("mul.rn.f32x2 %0, %0, %1;" : "+l"(d) : "l"(a));
}

// Scratch (device globals: allocation-free). 25.2 MB each, 75 MB total.
__device__ float g_q[(size_t)BB * HH * TT * SS];   // [b][h][t][d]
__device__ float g_k[(size_t)BB * HH * TT * SS];
__device__ float g_v[(size_t)BB * HH * TT * SS];

// ---------------------------------------------------------------------------
// Pass 1: Q/K/V = x @ W^T  (z selects which), output layout [b][h][t][d]
// 128x128 tile, BK=8, 256 threads, 8x8 per thread, packed f32x2 inner loop.
// ---------------------------------------------------------------------------
__global__ __launch_bounds__(256) void qkv_kernel(
    const float* __restrict__ x,
    const float* __restrict__ wq,
    const float* __restrict__ wk,
    const float* __restrict__ wv)
{
    __shared__ float As[8][132];
    __shared__ float Bs[8][132];

    const int which = blockIdx.z;
    const float* Wm = (which == 0) ? wq : (which == 1) ? wk : wv;
    float* dst = (which == 0) ? g_q : (which == 1) ? g_k : g_v;
    const float scale = (which == 0) ? 0.125f : 1.0f;  // 1/sqrt(64)

    const int rowBase = blockIdx.x * 128;
    const int colBase = blockIdx.y * 128;
    const int t  = threadIdx.x;
    const int tx = t & 15;
    const int ty = t >> 4;
    const int lr  = t >> 1;
    const int lk4 = (t & 1) * 4;

    f32x2_t acc2[8][4];
    #pragma unroll
    for (int i = 0; i < 8; i++)
        #pragma unroll
        for (int j = 0; j < 4; j++) acc2[i][j] = 0ull;

    for (int k0 = 0; k0 < EE; k0 += 8) {
        float4 av = *(const float4*)&x [(rowBase + lr) * EE + k0 + lk4];
        float4 bv = *(const float4*)&Wm[(colBase + lr) * EE + k0 + lk4];
        __syncthreads();
        As[lk4 + 0][lr] = av.x; As[lk4 + 1][lr] = av.y;
        As[lk4 + 2][lr] = av.z; As[lk4 + 3][lr] = av.w;
        Bs[lk4 + 0][lr] = bv.x; Bs[lk4 + 1][lr] = bv.y;
        Bs[lk4 + 2][lr] = bv.z; Bs[lk4 + 3][lr] = bv.w;
        __syncthreads();
        #pragma unroll
        for (int kk = 0; kk < 8; kk++) {
            float4 a0 = *(const float4*)&As[kk][ty * 8];
            float4 a1 = *(const float4*)&As[kk][ty * 8 + 4];
            f32x2_t ad[8];
            ad[0] = dup2(a0.x); ad[1] = dup2(a0.y);
            ad[2] = dup2(a0.z); ad[3] = dup2(a0.w);
            ad[4] = dup2(a1.x); ad[5] = dup2(a1.y);
            ad[6] = dup2(a1.z); ad[7] = dup2(a1.w);
            f32x2_t bp[4];
            #pragma unroll
            for (int j = 0; j < 4; j++)
                bp[j] = *(const f32x2_t*)&Bs[kk][tx * 8 + 2 * j];
            #pragma unroll
            for (int i = 0; i < 8; i++)
                #pragma unroll
                for (int j = 0; j < 4; j++) fma2(acc2[i][j], ad[i], bp[j]);
        }
    }

    #pragma unroll
    for (int i = 0; i < 8; i++) {
        const int n  = rowBase + ty * 8 + i;
        const int bb = n >> 12;
        const int tt = n & (TT - 1);
        #pragma unroll
        for (int j = 0; j < 4; j++) {
            float lo, hi;
            upk2(acc2[i][j], lo, hi);
            const int jc = colBase + tx * 8 + 2 * j;
            const int h  = jc >> 6;
            const int d  = jc & 63;
            float* base = &dst[(((size_t)(bb * HH + h) * TT) + tt) * SS];
            base[d]     = lo * scale;
            // jc+1 may cross a head boundary only if d==63; d is even here so safe
            base[d + 1] = hi * scale;
        }
    }
}

// ---------------------------------------------------------------------------
// Pass 2: fused flash-style attention, packed f32x2 math.
// Block = 128 queries (half a chunk) x one (b,h). Online softmax over 6 key
// tiles of 128 (prev/cur/next chunk). Zero-padded chunks contribute score 0
// (except triangular boundary mask = -1e30) to the denominator, with V = 0.
// P tile is stored TRANSPOSED (Pt[kcol][row]) with an XOR swizzle so the PV
// loop loads row-pairs as single LDS.64 with no duplication.
// ---------------------------------------------------------------------------
#define QK_STRIDE 132
#define V_STRIDE  68
#define PT_STRIDE 132
#define SM_K  (64 * QK_STRIDE)
#define SM_V  (SM_K + 64 * QK_STRIDE)
#define SM_P  (SM_V + 128 * V_STRIDE)
#define SMEM_FLOATS (SM_P + 128 * PT_STRIDE)
#define SMEM_BYTES  (SMEM_FLOATS * 4)

__global__ __launch_bounds__(256) void attn_kernel(float* __restrict__ out)
{
    extern __shared__ float sm[];
    float* Qs = sm;           // [64][QK_STRIDE]  Q transposed: Qs[d][row]
    float* Ks = sm + SM_K;    // [64][QK_STRIDE]  K transposed: Ks[d][col]
    float* Vs = sm + SM_V;    // [128][V_STRIDE]  V straight:  Vs[key][d]
    float* Pt = sm + SM_P;    // [128][PT_STRIDE] P transposed+swizzled: Pt[kcol][row^sw]

    const int c    = blockIdx.x >> 1;
    const int half = blockIdx.x & 1;
    const int bh   = blockIdx.y;
    const int b = bh / HH;
    const int h = bh % HH;

    const int t  = threadIdx.x;
    const int tx = t & 15;
    const int ty = t >> 4;

    const float* qptr = g_q + ((size_t)bh * TT + c * WW + half * 128) * SS;

    // Load Q tile transposed into SMEM (128 rows x 64 d)
    #pragma unroll
    for (int i = 0; i < 8; i++) {
        const int q  = t + i * 256;       // 0..2047
        const int r  = q >> 4;
        const int d4 = (q & 15) * 4;
        float4 v = *(const float4*)&qptr[r * SS + d4];
        Qs[(d4 + 0) * QK_STRIDE + r] = v.x;
        Qs[(d4 + 1) * QK_STRIDE + r] = v.y;
        Qs[(d4 + 2) * QK_STRIDE + r] = v.z;
        Qs[(d4 + 3) * QK_STRIDE + r] = v.w;
    }

    float m[8], l[8];
    f32x2_t o2[4][4];   // [row-pair][d]  rows (ty*8+2u, ty*8+2u+1), d = tx*4+j
    #pragma unroll
    for (int i = 0; i < 8; i++) { m[i] = -1e30f; l[i] = 0.0f; }
    #pragma unroll
    for (int u = 0; u < 4; u++)
        #pragma unroll
        for (int j = 0; j < 4; j++) o2[u][j] = 0ull;

    const int x0 = half * 128 + ty * 8;   // query index within chunk, base

    for (int nt = 0; nt < 6; nt++) {
        const int kc = c - 1 + (nt >> 1);
        const bool valid = (kc >= 0) && (kc < CC);
        const int y0 = (nt & 1) * 128;

        float s[8][8];

        if (valid) {
            const float* kptr = g_k + ((size_t)bh * TT + kc * WW + y0) * SS;
            const float* vptr = g_v + ((size_t)bh * TT + kc * WW + y0) * SS;
            __syncthreads();   // previous tile's PV / Pt reads done
            #pragma unroll
            for (int i = 0; i < 8; i++) {
                const int q  = t + i * 256;
                const int r  = q >> 4;
                const int d4 = (q & 15) * 4;
                float4 kv = *(const float4*)&kptr[r * SS + d4];
                Ks[(d4 + 0) * QK_STRIDE + r] = kv.x;
                Ks[(d4 + 1) * QK_STRIDE + r] = kv.y;
                Ks[(d4 + 2) * QK_STRIDE + r] = kv.z;
                Ks[(d4 + 3) * QK_STRIDE + r] = kv.w;
                *(float4*)&Vs[r * V_STRIDE + d4] = *(const float4*)&vptr[r * SS + d4];
            }
            __syncthreads();

            f32x2_t s2[8][4];
            #pragma unroll
            for (int i = 0; i < 8; i++)
                #pragma unroll
                for (int j = 0; j < 4; j++) s2[i][j] = 0ull;

            #pragma unroll 4
            for (int kk = 0; kk < 64; kk++) {
                float4 a0 = *(const float4*)&Qs[kk * QK_STRIDE + ty * 8];
                float4 a1 = *(const float4*)&Qs[kk * QK_STRIDE + ty * 8 + 4];
                f32x2_t ad[8];
                ad[0] = dup2(a0.x); ad[1] = dup2(a0.y);
                ad[2] = dup2(a0.z); ad[3] = dup2(a0.w);
                ad[4] = dup2(a1.x); ad[5] = dup2(a1.y);
                ad[6] = dup2(a1.z); ad[7] = dup2(a1.w);
                f32x2_t bp[4];
                #pragma unroll
                for (int j = 0; j < 4; j++)
                    bp[j] = *(const f32x2_t*)&Ks[kk * QK_STRIDE + tx * 8 + 2 * j];
                #pragma unroll
                for (int i = 0; i < 8; i++)
                    #pragma unroll
                    for (int j = 0; j < 4; j++) fma2(s2[i][j], ad[i], bp[j]);
            }
            #pragma unroll
            for (int i = 0; i < 8; i++)
                #pragma unroll
                for (int j = 0; j < 4; j++)
                    upk2(s2[i][j], s[i][2 * j], s[i][2 * j + 1]);
        } else {
            // Zero-padded neighbor chunk: score 0 except boundary mask.
            #pragma unroll
            for (int i = 0; i < 8; i++) {
                const int xq = x0 + i;
                #pragma unroll
                for (int j = 0; j < 8; j++) {
                    const int jg = nt * 128 + tx * 8 + j;
                    const bool msk = (c == 0) ? (jg < WW - xq)
                                              : (jg >= 3 * WW - 1 - xq);
                    s[i][j] = msk ? -1e30f : 0.0f;
                }
            }
        }

        // Online softmax update (16-thread row groups; xor masks 1..8 stay inside)
        float al[8];
        #pragma unroll
        for (int i = 0; i < 8; i++) {
            float rm = s[i][0];
            #pragma unroll
            for (int j = 1; j < 8; j++) rm = fmaxf(rm, s[i][j]);
            #pragma unroll
            for (int off = 8; off > 0; off >>= 1)
                rm = fmaxf(rm, __shfl_xor_sync(0xFFFFFFFFu, rm, off));
            const float mn = fmaxf(m[i], rm);
            al[i] = __expf(m[i] - mn);
            float rs = 0.0f;
            #pragma unroll
            for (int j = 0; j < 8; j++) {
                s[i][j] = __expf(s[i][j] - mn);
                rs += s[i][j];
            }
            #pragma unroll
            for (int off = 8; off > 0; off >>= 1)
                rs += __shfl_xor_sync(0xFFFFFFFFu, rs, off);
            l[i] = l[i] * al[i] + rs;
            m[i] = mn;
        }
        #pragma unroll
        for (int u = 0; u < 4; u++) {
            f32x2_t a2 = pk2(al[2 * u], al[2 * u + 1]);
            #pragma unroll
            for (int j = 0; j < 4; j++) mul2(o2[u][j], a2);
        }

        if (valid) {
            // Store P transposed with XOR swizzle: logical (kcol,row) lives at
            // Pt[kcol*PT_STRIDE + (row ^ (((kcol>>3)&3)<<3))].
            const int sw = (tx & 3) << 3;            // (kcol>>3)&3 == tx&3
            const int rbase = (ty * 8) ^ sw;
            #pragma unroll
            for (int j = 0; j < 8; j++) {
                float* pb = &Pt[(tx * 8 + j) * PT_STRIDE + rbase];
                *(float4*)pb       = make_float4(s[0][j], s[1][j], s[2][j], s[3][j]);
                *(float4*)(pb + 4) = make_float4(s[4][j], s[5][j], s[6][j], s[7][j]);
            }
            __syncthreads();

            #pragma unroll 4
            for (int kk = 0; kk < 128; kk++) {
                const int swk = ((kk >> 3) & 3) << 3;
                const int rb  = (ty * 8) ^ swk;
                f32x2_t ap[4];
                #pragma unroll
                for (int u = 0; u < 4; u++)
                    ap[u] = *(const f32x2_t*)&Pt[kk * PT_STRIDE + rb + 2 * u];
                float4 vv = *(const float4*)&Vs[kk * V_STRIDE + tx * 4];
                f32x2_t vd[4];
                vd[0] = dup2(vv.x); vd[1] = dup2(vv.y);
                vd[2] = dup2(vv.z); vd[3] = dup2(vv.w);
                #pragma unroll
                for (int u = 0; u < 4; u++)
                    #pragma unroll
                    for (int j = 0; j < 4; j++) fma2(o2[u][j], ap[u], vd[j]);
            }
        }
    }

    // Final normalize + write: out[b][t][h*64 + d]
    #pragma unroll
    for (int u = 0; u < 4; u++) {
        float o0[4], o1[4];
        #pragma unroll
        for (int j = 0; j < 4; j++) upk2(o2[u][j], o0[j], o1[j]);
        const float inv0 = 1.0f / l[2 * u];
        const float inv1 = 1.0f / l[2 * u + 1];
        const int trow0 = c * WW + half * 128 + ty * 8 + 2 * u;
        *(float4*)&out[((size_t)b * TT + trow0) * EE + h * SS + tx * 4] =
            make_float4(o0[0] * inv0, o0[1] * inv0, o0[2] * inv0, o0[3] * inv0);
        *(float4*)&out[((size_t)b * TT + trow0 + 1) * EE + h * SS + tx * 4] =
            make_float4(o1[0] * inv1, o1[1] * inv1, o1[2] * inv1, o1[3] * inv1);
    }
}

// ---------------------------------------------------------------------------
extern "C" void kernel_launch(void* const* d_in, const int* in_sizes, int n_in,
                              void* d_out, int out_size)
{
    const float* x  = (const float*)d_in[0];
    const float* wq = (const float*)d_in[1];
    const float* wk = (const float*)d_in[2];
    const float* wv = (const float*)d_in[3];
    float* out = (float*)d_out;

    cudaFuncSetAttribute(attn_kernel,
                         cudaFuncAttributeMaxDynamicSharedMemorySize, SMEM_BYTES);

    qkv_kernel<<<dim3(NN / 128, EE / 128, 3), 256>>>(x, wq, wk, wv);
    attn_kernel<<<dim3(2 * CC, BB * HH), 256, SMEM_BYTES>>>(out);
}

// round 5
// speedup vs baseline: 2.6865x; 2.6822x over previous
#include <cuda_runtime.h>
#include <cuda_bf16.h>

// Problem constants
#define BB 2
#define TT 4096
#define EE 768
#define HH 12
#define SS 64
#define WW 256
#define CC 16
#define NN (BB * TT)   // 8192

// ---------------------------------------------------------------------------
// Packed split-bf16 scratch (device globals: allocation-free)
// Each uint32 = bf16(hi) in low 16 bits | bf16(residual) in high 16 bits.
// ---------------------------------------------------------------------------
__device__ unsigned g_xp[(size_t)NN * EE];          // x packed          25.2 MB
__device__ unsigned g_wp[(size_t)3 * EE * EE];      // wq|wk|wv packed    7.1 MB
__device__ unsigned g_qp[(size_t)BB * HH * TT * SS];   // [b][h][t][d]
__device__ unsigned g_kp[(size_t)BB * HH * TT * SS];
__device__ unsigned g_vp[(size_t)BB * HH * TT * SS];

// ---------------------------------------------------------------------------
// Helpers
// ---------------------------------------------------------------------------
__device__ __forceinline__ unsigned pack2bf(float lo_elem, float hi_elem) {
    // returns bf16x2 reg: low half = bf16(lo_elem), high half = bf16(hi_elem)
    unsigned r;
    asm("cvt.rn.bf16x2.f32 %0, %1, %2;" : "=r"(r) : "f"(hi_elem), "f"(lo_elem));
    return r;
}
__device__ __forceinline__ unsigned pack_split(float v) {
    float hf = __bfloat162float(__float2bfloat16(v));
    return pack2bf(v, v - hf);   // low = hi-part, high = residual
}
__device__ __forceinline__ unsigned smaddr(const void* p) {
    return (unsigned)__cvta_generic_to_shared(p);
}
__device__ __forceinline__ void ldm_x4(unsigned a, unsigned& r0, unsigned& r1,
                                       unsigned& r2, unsigned& r3) {
    asm volatile("ldmatrix.sync.aligned.m8n8.x4.shared.b16 {%0,%1,%2,%3},[%4];"
                 : "=r"(r0), "=r"(r1), "=r"(r2), "=r"(r3) : "r"(a));
}
__device__ __forceinline__ void ldm_x4t(unsigned a, unsigned& r0, unsigned& r1,
                                        unsigned& r2, unsigned& r3) {
    asm volatile("ldmatrix.sync.aligned.m8n8.x4.trans.shared.b16 {%0,%1,%2,%3},[%4];"
                 : "=r"(r0), "=r"(r1), "=r"(r2), "=r"(r3) : "r"(a));
}
__device__ __forceinline__ void mma_bf16(float* d, const unsigned* a,
                                         unsigned b0, unsigned b1) {
    asm volatile(
        "mma.sync.aligned.m16n8k16.row.col.f32.bf16.bf16.f32 "
        "{%0,%1,%2,%3},{%4,%5,%6,%7},{%8,%9},{%0,%1,%2,%3};"
        : "+f"(d[0]), "+f"(d[1]), "+f"(d[2]), "+f"(d[3])
        : "r"(a[0]), "r"(a[1]), "r"(a[2]), "r"(a[3]), "r"(b0), "r"(b1));
}

// ---------------------------------------------------------------------------
// Pass 0: fp32 -> packed split-bf16 for x and the three weights, one launch.
// Writes the __device__ globals directly (no host symbol lookup needed).
// ---------------------------------------------------------------------------
#define NX4 (NN * EE / 4)        // 1,572,864 float4s of x
#define NW4 (EE * EE / 4)        //   147,456 float4s per weight
#define NTOT4 (NX4 + 3 * NW4)

__global__ __launch_bounds__(256) void convert_kernel(
    const float* __restrict__ x,  const float* __restrict__ wq,
    const float* __restrict__ wk, const float* __restrict__ wv)
{
    int i = blockIdx.x * 256 + threadIdx.x;
    if (i >= NTOT4) return;
    const float4* src;
    unsigned* dstbase;
    int j;
    if (i < NX4)                  { src = (const float4*)x;  dstbase = g_xp;              j = i; }
    else if (i < NX4 + NW4)       { src = (const float4*)wq; dstbase = g_wp;              j = i - NX4; }
    else if (i < NX4 + 2 * NW4)   { src = (const float4*)wk; dstbase = g_wp + EE * EE;     j = i - NX4 - NW4; }
    else                          { src = (const float4*)wv; dstbase = g_wp + 2 * EE * EE; j = i - NX4 - 2 * NW4; }
    float4 v = src[j];
    uint4 o;
    o.x = pack_split(v.x); o.y = pack_split(v.y);
    o.z = pack_split(v.z); o.w = pack_split(v.w);
    ((uint4*)dstbase)[j] = o;
}

// ---------------------------------------------------------------------------
// Pass 1: Q/K/V = x @ W^T via mma.sync bf16, split accumulation (3 mma).
// 128x128 tile, k-step 16, 256 threads = 8 warps (2x4), warp tile 64x32.
// Epilogue writes packed split-bf16 to g_qp/g_kp/g_vp in [b][h][t][d].
// ---------------------------------------------------------------------------
#define QST 24   // smem row stride (bf16 elems) for 16-wide k tiles

__global__ __launch_bounds__(256) void qkv_mma_kernel()
{
    __shared__ __nv_bfloat16 Ah[128 * QST], Al[128 * QST];
    __shared__ __nv_bfloat16 Bh[128 * QST], Bl[128 * QST];

    const int which = blockIdx.z;
    const unsigned* wp = g_wp + (size_t)which * EE * EE;
    unsigned* dst = (which == 0) ? g_qp : (which == 1) ? g_kp : g_vp;
    const float scale = (which == 0) ? 0.125f : 1.0f;

    const int rowBase = blockIdx.x * 128;
    const int colBase = blockIdx.y * 128;
    const int t    = threadIdx.x;
    const int lane = t & 31;
    const int w    = t >> 5;
    const int wm   = (w >> 2) * 64;
    const int wn   = (w & 3) * 32;

    float acc[4][4][4];
    #pragma unroll
    for (int mt = 0; mt < 4; mt++)
        #pragma unroll
        for (int nt = 0; nt < 4; nt++)
            #pragma unroll
            for (int e = 0; e < 4; e++) acc[mt][nt][e] = 0.0f;

    uint4 pa[2], pb[2];
    // prologue load (k0 = 0)
    #pragma unroll
    for (int j = 0; j < 2; j++) {
        const int s   = t + j * 256;
        const int row = s >> 2;
        const int q4  = (s & 3) * 4;
        pa[j] = *(const uint4*)&g_xp[(size_t)(rowBase + row) * EE + q4];
        pb[j] = *(const uint4*)&wp  [(size_t)(colBase + row) * EE + q4];
    }

    for (int k0 = 0; k0 < EE; k0 += 16) {
        __syncthreads();
        #pragma unroll
        for (int j = 0; j < 2; j++) {
            const int s   = t + j * 256;
            const int row = s >> 2;
            const int q4  = (s & 3) * 4;
            *(unsigned*)&Ah[row * QST + q4]     = __byte_perm(pa[j].x, pa[j].y, 0x5410);
            *(unsigned*)&Ah[row * QST + q4 + 2] = __byte_perm(pa[j].z, pa[j].w, 0x5410);
            *(unsigned*)&Al[row * QST + q4]     = __byte_perm(pa[j].x, pa[j].y, 0x7632);
            *(unsigned*)&Al[row * QST + q4 + 2] = __byte_perm(pa[j].z, pa[j].w, 0x7632);
            *(unsigned*)&Bh[row * QST + q4]     = __byte_perm(pb[j].x, pb[j].y, 0x5410);
            *(unsigned*)&Bh[row * QST + q4 + 2] = __byte_perm(pb[j].z, pb[j].w, 0x5410);
            *(unsigned*)&Bl[row * QST + q4]     = __byte_perm(pb[j].x, pb[j].y, 0x7632);
            *(unsigned*)&Bl[row * QST + q4 + 2] = __byte_perm(pb[j].z, pb[j].w, 0x7632);
        }
        __syncthreads();

        if (k0 + 16 < EE) {
            #pragma unroll
            for (int j = 0; j < 2; j++) {
                const int s   = t + j * 256;
                const int row = s >> 2;
                const int q4  = (s & 3) * 4;
                pa[j] = *(const uint4*)&g_xp[(size_t)(rowBase + row) * EE + k0 + 16 + q4];
                pb[j] = *(const uint4*)&wp  [(size_t)(colBase + row) * EE + k0 + 16 + q4];
            }
        }

        unsigned ah[4][4], al[4][4], bh[2][4], bl[2][4];
        #pragma unroll
        for (int mt = 0; mt < 4; mt++) {
            const int off = (wm + mt * 16 + (lane & 15)) * QST + ((lane >> 4) << 3);
            ldm_x4(smaddr(&Ah[off]), ah[mt][0], ah[mt][1], ah[mt][2], ah[mt][3]);
            ldm_x4(smaddr(&Al[off]), al[mt][0], al[mt][1], al[mt][2], al[mt][3]);
        }
        #pragma unroll
        for (int g = 0; g < 2; g++) {
            const int off = (wn + g * 16 + ((lane >> 4) << 3) + (lane & 7)) * QST
                          + (((lane >> 3) & 1) << 3);
            ldm_x4(smaddr(&Bh[off]), bh[g][0], bh[g][1], bh[g][2], bh[g][3]);
            ldm_x4(smaddr(&Bl[off]), bl[g][0], bl[g][1], bl[g][2], bl[g][3]);
        }
        #pragma unroll
        for (int mt = 0; mt < 4; mt++)
            #pragma unroll
            for (int nt = 0; nt < 4; nt++) {
                const int g  = nt >> 1;
                const int hb = (nt & 1) * 2;
                mma_bf16(acc[mt][nt], ah[mt], bh[g][hb], bh[g][hb + 1]);
                mma_bf16(acc[mt][nt], al[mt], bh[g][hb], bh[g][hb + 1]);
                mma_bf16(acc[mt][nt], ah[mt], bl[g][hb], bl[g][hb + 1]);
            }
    }

    // epilogue: pack split + store [b][h][t][d]
    #pragma unroll
    for (int mt = 0; mt < 4; mt++) {
        const int rg0 = rowBase + wm + mt * 16 + (lane >> 2);
        #pragma unroll
        for (int nt = 0; nt < 4; nt++) {
            const int jc = colBase + wn + nt * 8 + (lane & 3) * 2;
            const int h  = jc >> 6;
            const int d  = jc & 63;
            #pragma unroll
            for (int rh = 0; rh < 2; rh++) {
                const int rg = rg0 + rh * 8;
                const int bb = rg >> 12;
                const int tt = rg & (TT - 1);
                uint2 pv;
                pv.x = pack_split(acc[mt][nt][rh * 2 + 0] * scale);
                pv.y = pack_split(acc[mt][nt][rh * 2 + 1] * scale);
                *(uint2*)&dst[(((size_t)(bb * HH + h) * TT) + tt) * SS + d] = pv;
            }
        }
    }
}

// ---------------------------------------------------------------------------
// Pass 2: fused flash attention, all-mma. Block = 128 q x (b,h); 8 warps,
// warp = 16 q rows x 128 keys per tile. 6 key tiles of 128. Split-bf16.
// ---------------------------------------------------------------------------
#define KST 72                     // smem row stride (bf16) for 64/128-wide tiles
#define ATT_SMEM_ELEMS (4 * 128 * KST)
#define ATT_SMEM_BYTES (ATT_SMEM_ELEMS * 2)

__global__ __launch_bounds__(256) void attn_mma_kernel(float* __restrict__ out)
{
    extern __shared__ __nv_bfloat16 sm[];
    __nv_bfloat16* Kh = sm;
    __nv_bfloat16* Kl = sm + 128 * KST;
    __nv_bfloat16* Vh = sm + 2 * 128 * KST;
    __nv_bfloat16* Vl = sm + 3 * 128 * KST;

    const int c    = blockIdx.x >> 1;
    const int half = blockIdx.x & 1;
    const int bh   = blockIdx.y;
    const int b = bh / HH;
    const int h = bh % HH;

    const int t    = threadIdx.x;
    const int lane = t & 31;
    const int w    = t >> 5;

    // ---- stage Q (128x64) into Kh/Kl, build register-resident Q frags ----
    {
        const unsigned* qb = g_qp + ((size_t)bh * TT + c * WW + half * 128) * SS;
        #pragma unroll
        for (int i = 0; i < 8; i++) {
            const int s   = t + i * 256;
            const int row = s >> 4;
            const int q4  = (s & 15) * 4;
            uint4 v = *(const uint4*)&qb[row * SS + q4];
            *(unsigned*)&Kh[row * KST + q4]     = __byte_perm(v.x, v.y, 0x5410);
            *(unsigned*)&Kh[row * KST + q4 + 2] = __byte_perm(v.z, v.w, 0x5410);
            *(unsigned*)&Kl[row * KST + q4]     = __byte_perm(v.x, v.y, 0x7632);
            *(unsigned*)&Kl[row * KST + q4 + 2] = __byte_perm(v.z, v.w, 0x7632);
        }
    }
    __syncthreads();

    unsigned qh[4][4], ql[4][4];
    #pragma unroll
    for (int kt = 0; kt < 4; kt++) {
        const int off = (w * 16 + (lane & 15)) * KST + kt * 16 + ((lane >> 4) << 3);
        ldm_x4(smaddr(&Kh[off]), qh[kt][0], qh[kt][1], qh[kt][2], qh[kt][3]);
        ldm_x4(smaddr(&Kl[off]), ql[kt][0], ql[kt][1], ql[kt][2], ql[kt][3]);
    }

    float m0 = -1e30f, m1 = -1e30f, l0 = 0.0f, l1 = 0.0f;
    float o_fr[8][4];
    #pragma unroll
    for (int nd = 0; nd < 8; nd++)
        #pragma unroll
        for (int e = 0; e < 4; e++) o_fr[nd][e] = 0.0f;

    const int xq0 = half * 128 + w * 16 + (lane >> 2);  // row of c0/c1

    for (int nt = 0; nt < 6; nt++) {
        const int kc = c - 1 + (nt >> 1);
        const bool valid = (kc >= 0) && (kc < CC);

        float s_fr[16][4];

        if (valid) {
            const int y0 = (nt & 1) * 128;
            const unsigned* kb = g_kp + ((size_t)bh * TT + kc * WW + y0) * SS;
            const unsigned* vb = g_vp + ((size_t)bh * TT + kc * WW + y0) * SS;

            __syncthreads();   // everyone done with smem from prior tile / Q frags
            #pragma unroll
            for (int i = 0; i < 8; i++) {
                const int s   = t + i * 256;
                const int row = s >> 4;
                const int q4  = (s & 15) * 4;
                uint4 kv = *(const uint4*)&kb[row * SS + q4];
                uint4 vv = *(const uint4*)&vb[row * SS + q4];
                *(unsigned*)&Kh[row * KST + q4]     = __byte_perm(kv.x, kv.y, 0x5410);
                *(unsigned*)&Kh[row * KST + q4 + 2] = __byte_perm(kv.z, kv.w, 0x5410);
                *(unsigned*)&Kl[row * KST + q4]     = __byte_perm(kv.x, kv.y, 0x7632);
                *(unsigned*)&Kl[row * KST + q4 + 2] = __byte_perm(kv.z, kv.w, 0x7632);
                *(unsigned*)&Vh[row * KST + q4]     = __byte_perm(vv.x, vv.y, 0x5410);
                *(unsigned*)&Vh[row * KST + q4 + 2] = __byte_perm(vv.z, vv.w, 0x5410);
                *(unsigned*)&Vl[row * KST + q4]     = __byte_perm(vv.x, vv.y, 0x7632);
                *(unsigned*)&Vl[row * KST + q4 + 2] = __byte_perm(vv.z, vv.w, 0x7632);
            }
            __syncthreads();

            #pragma unroll
            for (int n = 0; n < 16; n++)
                #pragma unroll
                for (int e = 0; e < 4; e++) s_fr[n][e] = 0.0f;

            #pragma unroll
            for (int kt = 0; kt < 4; kt++) {
                #pragma unroll
                for (int g = 0; g < 8; g++) {
                    unsigned kbf[4], klf[4];
                    const int off = (g * 16 + ((lane >> 4) << 3) + (lane & 7)) * KST
                                  + kt * 16 + (((lane >> 3) & 1) << 3);
                    ldm_x4(smaddr(&Kh[off]), kbf[0], kbf[1], kbf[2], kbf[3]);
                    ldm_x4(smaddr(&Kl[off]), klf[0], klf[1], klf[2], klf[3]);
                    #pragma unroll
                    for (int h2 = 0; h2 < 2; h2++) {
                        const int n = g * 2 + h2;
                        mma_bf16(s_fr[n], qh[kt], kbf[h2 * 2], kbf[h2 * 2 + 1]);
                        mma_bf16(s_fr[n], ql[kt], kbf[h2 * 2], kbf[h2 * 2 + 1]);
                        mma_bf16(s_fr[n], qh[kt], klf[h2 * 2], klf[h2 * 2 + 1]);
                    }
                }
            }
        } else {
            // zero-padded neighbor chunk: score 0, boundary mask -1e30
            #pragma unroll
            for (int n = 0; n < 16; n++) {
                const int jg = nt * 128 + n * 8 + (lane & 3) * 2;
                #pragma unroll
                for (int e = 0; e < 4; e++) {
                    const int xq = xq0 + (e >> 1) * 8;
                    const int j  = jg + (e & 1);
                    const bool msk = (c == 0) ? (j < WW - xq)
                                              : (j >= 3 * WW - 1 - xq);
                    s_fr[n][e] = msk ? -1e30f : 0.0f;
                }
            }
        }

        // ---- online softmax on fragments ----
        float rm0 = -1e30f, rm1 = -1e30f;
        #pragma unroll
        for (int n = 0; n < 16; n++) {
            rm0 = fmaxf(rm0, fmaxf(s_fr[n][0], s_fr[n][1]));
            rm1 = fmaxf(rm1, fmaxf(s_fr[n][2], s_fr[n][3]));
        }
        #pragma unroll
        for (int off = 1; off <= 2; off <<= 1) {
            rm0 = fmaxf(rm0, __shfl_xor_sync(0xFFFFFFFFu, rm0, off));
            rm1 = fmaxf(rm1, __shfl_xor_sync(0xFFFFFFFFu, rm1, off));
        }
        const float mn0 = fmaxf(m0, rm0);
        const float mn1 = fmaxf(m1, rm1);
        const float al0 = __expf(m0 - mn0);
        const float al1 = __expf(m1 - mn1);
        float rs0 = 0.0f, rs1 = 0.0f;
        #pragma unroll
        for (int n = 0; n < 16; n++) {
            s_fr[n][0] = __expf(s_fr[n][0] - mn0);
            s_fr[n][1] = __expf(s_fr[n][1] - mn0);
            s_fr[n][2] = __expf(s_fr[n][2] - mn1);
            s_fr[n][3] = __expf(s_fr[n][3] - mn1);
            rs0 += s_fr[n][0] + s_fr[n][1];
            rs1 += s_fr[n][2] + s_fr[n][3];
        }
        #pragma unroll
        for (int off = 1; off <= 2; off <<= 1) {
            rs0 += __shfl_xor_sync(0xFFFFFFFFu, rs0, off);
            rs1 += __shfl_xor_sync(0xFFFFFFFFu, rs1, off);
        }
        l0 = l0 * al0 + rs0;  m0 = mn0;
        l1 = l1 * al1 + rs1;  m1 = mn1;
        #pragma unroll
        for (int nd = 0; nd < 8; nd++) {
            o_fr[nd][0] *= al0; o_fr[nd][1] *= al0;
            o_fr[nd][2] *= al1; o_fr[nd][3] *= al1;
        }

        if (valid) {
            // ---- O += P @ V (split P, split V; 3 mma) ----
            #pragma unroll
            for (int ktj = 0; ktj < 8; ktj++) {
                const float* pe = s_fr[2 * ktj];
                const float* po = s_fr[2 * ktj + 1];
                float heA = __bfloat162float(__float2bfloat16(pe[0]));
                float heB = __bfloat162float(__float2bfloat16(pe[1]));
                float heC = __bfloat162float(__float2bfloat16(pe[2]));
                float heD = __bfloat162float(__float2bfloat16(pe[3]));
                float hoA = __bfloat162float(__float2bfloat16(po[0]));
                float hoB = __bfloat162float(__float2bfloat16(po[1]));
                float hoC = __bfloat162float(__float2bfloat16(po[2]));
                float hoD = __bfloat162float(__float2bfloat16(po[3]));
                unsigned pah[4], pal[4];
                pah[0] = pack2bf(pe[0], pe[1]);
                pah[1] = pack2bf(pe[2], pe[3]);
                pah[2] = pack2bf(po[0], po[1]);
                pah[3] = pack2bf(po[2], po[3]);
                pal[0] = pack2bf(pe[0] - heA, pe[1] - heB);
                pal[1] = pack2bf(pe[2] - heC, pe[3] - heD);
                pal[2] = pack2bf(po[0] - hoA, po[1] - hoB);
                pal[3] = pack2bf(po[2] - hoC, po[3] - hoD);

                #pragma unroll
                for (int g = 0; g < 4; g++) {
                    unsigned vbf[4], vlf[4];
                    const int off = (ktj * 16 + (lane & 15)) * KST
                                  + g * 16 + ((lane >> 4) << 3);
                    ldm_x4t(smaddr(&Vh[off]), vbf[0], vbf[1], vbf[2], vbf[3]);
                    ldm_x4t(smaddr(&Vl[off]), vlf[0], vlf[1], vlf[2], vlf[3]);
                    #pragma unroll
                    for (int h2 = 0; h2 < 2; h2++) {
                        const int nd = g * 2 + h2;
                        mma_bf16(o_fr[nd], pah, vbf[h2 * 2], vbf[h2 * 2 + 1]);
                        mma_bf16(o_fr[nd], pal, vbf[h2 * 2], vbf[h2 * 2 + 1]);
                        mma_bf16(o_fr[nd], pah, vlf[h2 * 2], vlf[h2 * 2 + 1]);
                    }
                }
            }
        }
    }

    // ---- epilogue: normalize + store fp32 ----
    const float inv0 = 1.0f / l0;
    const float inv1 = 1.0f / l1;
    const int tr0 = c * WW + half * 128 + w * 16 + (lane >> 2);
    #pragma unroll
    for (int nd = 0; nd < 8; nd++) {
        const int d0 = nd * 8 + (lane & 3) * 2;
        *(float2*)&out[((size_t)b * TT + tr0) * EE + h * SS + d0] =
            make_float2(o_fr[nd][0] * inv0, o_fr[nd][1] * inv0);
        *(float2*)&out[((size_t)b * TT + tr0 + 8) * EE + h * SS + d0] =
            make_float2(o_fr[nd][2] * inv1, o_fr[nd][3] * inv1);
    }
}

// ---------------------------------------------------------------------------
extern "C" void kernel_launch(void* const* d_in, const int* in_sizes, int n_in,
                              void* d_out, int out_size)
{
    const float* x  = (const float*)d_in[0];
    const float* wq = (const float*)d_in[1];
    const float* wk = (const float*)d_in[2];
    const float* wv = (const float*)d_in[3];
    float* out = (float*)d_out;

    cudaFuncSetAttribute(attn_mma_kernel,
                         cudaFuncAttributeMaxDynamicSharedMemorySize, ATT_SMEM_BYTES);

    convert_kernel<<<(NTOT4 + 255) / 256, 256>>>(x, wq, wk, wv);
    qkv_mma_kernel<<<dim3(NN / 128, EE / 128, 3), 256>>>();
    attn_mma_kernel<<<dim3(2 * CC, BB * HH), 256, ATT_SMEM_BYTES>>>(out);
}